// round 5
// baseline (speedup 1.0000x reference)
#include <cuda_runtime.h>
#include <cstdint>

// DocREDModel: entity-pool -> tanh-projection -> block-bilinear classifier
// B=16 S=2048 H=768 E=32 M=4 P=128 L=97 BLOCK=64
//
//  k1: ent (512x768) dedup-weighted gather-sum
//  k2: zh = tanh(ent@Wh+bh), zt = tanh(ent@Wt+bt)  (packed f32x2, dup-B)
//  k3: out = bc broadcast
//  k4: l=96 column, full-chip (32 n-tiles x 12 cb = 384 blocks)
//  k5: bilinear GEMM l=0..95: STATIC partition of 12288 (nt,cb,ii) atoms over
//      296 CTAs (contiguous ranges -> b2-tile reuse, one acc flush per nt).
//      Warp tile 64n x 16l, dup-pair Ws broadcasts, packed f32x2 FMA.

#define B_    16
#define S_    2048
#define H_    768
#define E_    32
#define L_    97
#define NROWS 2048
#define NENT  512

typedef unsigned long long ull;

__device__ float g_ent[NENT * H_];
__device__ float g_zh[NENT * H_];
__device__ float g_zt[NENT * H_];

__device__ __forceinline__ ull ffma2(ull a, ull b, ull c) {
    ull d; asm("fma.rn.f32x2 %0, %1, %2, %3;" : "=l"(d) : "l"(a), "l"(b), "l"(c));
    return d;
}
__device__ __forceinline__ ull fmul2(ull a, ull b) {
    ull d; asm("mul.rn.f32x2 %0, %1, %2;" : "=l"(d) : "l"(a), "l"(b));
    return d;
}
__device__ __forceinline__ ull fpack(float x, float y) {
    ull d; asm("mov.b64 %0, {%1, %2};" : "=l"(d) : "f"(x), "f"(y));
    return d;
}
__device__ __forceinline__ ull fsplat(float x) {
    ull d; asm("mov.b64 %0, {%1, %1};" : "=l"(d) : "f"(x));
    return d;
}
__device__ __forceinline__ float lo32(ull v) { return __uint_as_float((unsigned)(v & 0xffffffffull)); }
__device__ __forceinline__ float hi32(ull v) { return __uint_as_float((unsigned)(v >> 32)); }

// ---------------------------------------------------------------- kernel 1
__global__ void build_ent_kernel(const float* __restrict__ feats,
                                 const int* __restrict__ pos) {
    int be = blockIdx.x;
    int b  = be >> 5;
    const int* pp = pos + be * 4;
    int p0 = pp[0], p1 = pp[1], p2 = pp[2], p3 = pp[3];
    float w1 = (p1 != p0) ? 1.f : 0.f;
    float w2 = (p2 != p0 && p2 != p1) ? 1.f : 0.f;
    float w3 = (p3 != p0 && p3 != p1 && p3 != p2) ? 1.f : 0.f;
    const float* base = feats + (size_t)b * S_ * H_;
    const float4* r0 = (const float4*)(base + (size_t)p0 * H_);
    const float4* r1 = (const float4*)(base + (size_t)p1 * H_);
    const float4* r2 = (const float4*)(base + (size_t)p2 * H_);
    const float4* r3 = (const float4*)(base + (size_t)p3 * H_);
    int t = threadIdx.x;   // 192 threads * float4 = 768
    float4 v0 = r0[t], v1 = r1[t], v2 = r2[t], v3 = r3[t];
    float4 o;
    o.x = v0.x + w1 * v1.x + w2 * v2.x + w3 * v3.x;
    o.y = v0.y + w1 * v1.y + w2 * v2.y + w3 * v3.y;
    o.z = v0.z + w1 * v1.z + w2 * v2.z + w3 * v3.z;
    o.w = v0.w + w1 * v1.w + w2 * v2.w + w3 * v3.w;
    ((float4*)(g_ent + (size_t)be * H_))[t] = o;
}

// ---------------------------------------------------------------- kernel 2
__global__ void __launch_bounds__(256)
gemm_tanh_kernel(const float* __restrict__ Wh, const float* __restrict__ bh,
                 const float* __restrict__ Wt, const float* __restrict__ bt) {
    const float* W    = blockIdx.z ? Wt : Wh;
    const float* bias = blockIdx.z ? bt : bh;
    float*       Z    = blockIdx.z ? g_zt : g_zh;

    __shared__ float AsT[16 * 68];
    __shared__ float Bd[16 * 256];

    int tid = threadIdx.x;
    int mg  = tid & 15;
    int ng  = tid >> 4;
    int m0  = blockIdx.x * 64;
    int n0  = blockIdx.y * 128;

    ull acc[2][8];
#pragma unroll
    for (int p = 0; p < 2; p++)
#pragma unroll
        for (int c = 0; c < 8; c++) acc[p][c] = 0ull;

    for (int k0 = 0; k0 < H_; k0 += 16) {
        __syncthreads();
#pragma unroll
        for (int e = tid; e < 1024; e += 256) {
            int kk = e & 15, m = e >> 4;
            AsT[kk * 68 + m] = g_ent[(m0 + m) * H_ + k0 + kk];
        }
#pragma unroll
        for (int e = tid; e < 2048; e += 256) {
            int n = e & 127, kk = e >> 7;
            float w = W[(k0 + kk) * H_ + n0 + n];
            ((float2*)Bd)[kk * 128 + n] = make_float2(w, w);
        }
        __syncthreads();
#pragma unroll
        for (int kk = 0; kk < 16; kk++) {
            ulonglong2 av = *(const ulonglong2*)&AsT[kk * 68 + mg * 4];
            const ulonglong2* wp = (const ulonglong2*)&Bd[kk * 256 + ng * 16];
            ulonglong2 w01 = wp[0], w23 = wp[1], w45 = wp[2], w67 = wp[3];
            ull w[8] = {w01.x, w01.y, w23.x, w23.y, w45.x, w45.y, w67.x, w67.y};
#pragma unroll
            for (int c = 0; c < 8; c++) {
                acc[0][c] = ffma2(av.x, w[c], acc[0][c]);
                acc[1][c] = ffma2(av.y, w[c], acc[1][c]);
            }
        }
    }
#pragma unroll
    for (int p = 0; p < 2; p++) {
#pragma unroll
        for (int c = 0; c < 8; c++) {
            int n = n0 + ng * 8 + c;
            float bv = bias[n];
            int m = m0 + mg * 4 + 2 * p;
            Z[m * H_ + n]       = tanhf(lo32(acc[p][c]) + bv);
            Z[(m + 1) * H_ + n] = tanhf(hi32(acc[p][c]) + bv);
        }
    }
}

// ---------------------------------------------------------------- kernel 3
__global__ void init_out_kernel(const float* __restrict__ bc, float* __restrict__ out) {
    int i = blockIdx.x * blockDim.x + threadIdx.x;
    if (i < NROWS * L_) out[i] = bc[i % L_];
}

// ---------------------------------------------------------------- kernel 4
// l=96 column.  Grid (32 n-tiles of 64, 12 cb), 256 threads.
// thread: ngp=tid&15 (4 n as 2 pairs), slice=tid>>4 (4 i-rows each).
#define L96_SMEM ((4096 * 3) * 4 + 512)
__global__ void __launch_bounds__(256)
l96_kernel(const int* __restrict__ ht, const float* __restrict__ Wc,
           float* __restrict__ out) {
    extern __shared__ float s4[];
    float* b1c = s4;               // [i][n] stride 64
    float* b2c = s4 + 4096;        // [j][n] stride 64
    float* w96 = s4 + 8192;        // [4096]
    int*   rh  = (int*)(s4 + 12288);
    int*   rt  = rh + 64;

    int tid = threadIdx.x;
    int nb  = blockIdx.x * 64;
    int cb  = blockIdx.y;

    if (tid < 64) {
        int g = nb + tid;
        int b = g >> 7;
        rh[tid] = b * E_ + ht[2 * g];
        rt[tid] = b * E_ + ht[2 * g + 1];
    }
    __syncthreads();

    for (int e = tid; e < 4096; e += 256) {
        int n = e >> 6, i = e & 63;
        b1c[i * 64 + n] = g_zh[rh[n] * H_ + cb * 64 + i];
        b2c[i * 64 + n] = g_zt[rt[n] * H_ + cb * 64 + i];
    }
    for (int e = tid; e < 4096; e += 256)
        w96[e] = Wc[(size_t)(cb * 4096 + e) * L_ + 96];
    __syncthreads();

    int ngp  = tid & 15;
    int nloc = ngp * 4;
    int i0   = (tid >> 4) * 4;
    ull acc0 = 0, acc1 = 0;

#pragma unroll
    for (int i = 0; i < 4; i++) {
        int ig = i0 + i;
        ulonglong2 b1p = *(const ulonglong2*)&b1c[ig * 64 + nloc];
        const float* wr = &w96[ig * 64];
#pragma unroll 8
        for (int j = 0; j < 64; j++) {
            ulonglong2 q = *(const ulonglong2*)&b2c[j * 64 + nloc];
            ull wp = fsplat(wr[j]);
            acc0 = ffma2(fmul2(q.x, b1p.x), wp, acc0);
            acc1 = ffma2(fmul2(q.y, b1p.y), wp, acc1);
        }
    }
    int n0 = nb + nloc;
    atomicAdd(&out[(n0 + 0) * L_ + 96], lo32(acc0));
    atomicAdd(&out[(n0 + 1) * L_ + 96], hi32(acc0));
    atomicAdd(&out[(n0 + 2) * L_ + 96], lo32(acc1));
    atomicAdd(&out[(n0 + 3) * L_ + 96], hi32(acc1));
}

// ---------------------------------------------------------------- kernel 5
// Bilinear GEMM, l=0..95.  12288 atoms = 16 nt x 12 cb x 64 ii, statically
// partitioned into 296 contiguous ranges (all CTAs resident at 2/SM).
// 384 thr = 12 warps: warp w -> l-block (w%6)*16, n-half (w/6)*64.
// Lane owns one n-pair (2 rows).  b2 tile + dup-pair Ws in smem; b1 pair per
// atom straight from gmem.  acc persists across atoms of the same nt.

#define BSTRIDE 130
#define K5_B2_F  (64 * BSTRIDE)            // 8320 floats
#define K5_WS_F  (64 * 192)                // 12288 floats (dup pairs)
#define K5_SMEM_BYTES ((K5_B2_F + K5_WS_F) * 4 + 256 * 4)
#define ATOMS_TOTAL (16 * 12 * 64)         // 12288
#define NCTAS 296

__global__ void __launch_bounds__(384, 2)
bilinear_kernel(const int* __restrict__ ht, const float* __restrict__ Wc,
                float* __restrict__ out) {
    extern __shared__ float sm[];
    float* b2T = sm;                        // [j][n] stride 130
    float* Wsd = sm + K5_B2_F;              // [j][96 dup pairs] stride 192 fl
    int*   rh  = (int*)(sm + K5_B2_F + K5_WS_F);
    int*   rt  = rh + 128;

    int tid  = threadIdx.x;
    int warp = tid >> 5;
    int lane = tid & 31;
    int lb   = warp % 6;                    // l-block
    int nh   = warp / 6;                    // n-half
    int l0   = lb * 16;
    int nloc = nh * 64 + lane * 2;          // local row pair
    int lfill = tid % 96;
    int jf0   = tid / 96;                   // 0..3

    int c  = blockIdx.x;
    int a0 = (int)(((long long)c * ATOMS_TOTAL) / NCTAS);
    int a1 = (int)(((long long)(c + 1) * ATOMS_TOTAL) / NCTAS);

    int cur_nt = -1, cur_cb = -1;
    int r0 = 0, r1 = 0;
    ull acc[16];
#pragma unroll
    for (int q = 0; q < 16; q++) acc[q] = 0ull;

    for (int a = a0; a < a1; a++) {
        int nt  = a / 768;
        int rem = a - nt * 768;
        int cb  = rem >> 6;
        int ii  = rem & 63;

        if (cb != cur_cb || nt != cur_nt) {
            if (nt != cur_nt) {
                if (cur_nt >= 0) {
                    int gn = cur_nt * 128 + nloc;
#pragma unroll
                    for (int q = 0; q < 16; q++) {
                        atomicAdd(&out[gn * L_ + l0 + q], lo32(acc[q]));
                        atomicAdd(&out[(gn + 1) * L_ + l0 + q], hi32(acc[q]));
                        acc[q] = 0ull;
                    }
                }
                __syncthreads();            // prior smem reads done
                if (tid < 128) {
                    int g = nt * 128 + tid; // batch b == nt (128 rows per batch)
                    rh[tid] = nt * E_ + ht[2 * g];
                    rt[tid] = nt * E_ + ht[2 * g + 1];
                }
                __syncthreads();            // rh/rt ready
                r0 = rh[nloc] * H_;
                r1 = rh[nloc + 1] * H_;
                cur_nt = nt;
            } else {
                __syncthreads();            // prior b2T reads done
            }
            for (int e = tid; e < 8192; e += 384) {
                int n = e >> 6, j = e & 63;
                b2T[j * BSTRIDE + n] = g_zt[rt[n] * H_ + cb * 64 + j];
            }
            cur_cb = cb;                    // visibility via the Wsd sync below
        }

        int col = cb * 64 + ii;
        __syncthreads();                    // prior Wsd reads done; b2T visible
        {
            int k0 = col * 64;
            const float* wc = Wc + (size_t)k0 * L_ + lfill;
#pragma unroll
            for (int s = 0; s < 16; s++) {
                int j = jf0 + s * 4;
                float w = wc[(size_t)j * L_];
                ((float2*)Wsd)[j * 96 + lfill] = make_float2(w, w);
            }
        }
        ull b1p = fpack(g_zh[r0 + col], g_zh[r1 + col]);
        __syncthreads();                    // Wsd ready

#pragma unroll 4
        for (int j = 0; j < 64; j++) {
            ull q = *(const ull*)(b2T + j * BSTRIDE + nloc);
            ull aa = fmul2(q, b1p);
            const ulonglong2* wp = (const ulonglong2*)(Wsd + j * 192 + lb * 32);
            ulonglong2 w01 = wp[0], w23 = wp[1], w45 = wp[2], w67 = wp[3];
            acc[0]  = ffma2(aa, w01.x, acc[0]);
            acc[1]  = ffma2(aa, w01.y, acc[1]);
            acc[2]  = ffma2(aa, w23.x, acc[2]);
            acc[3]  = ffma2(aa, w23.y, acc[3]);
            acc[4]  = ffma2(aa, w45.x, acc[4]);
            acc[5]  = ffma2(aa, w45.y, acc[5]);
            acc[6]  = ffma2(aa, w67.x, acc[6]);
            acc[7]  = ffma2(aa, w67.y, acc[7]);
            const ulonglong2* wp2 = wp + 4;
            ulonglong2 v01 = wp2[0], v23 = wp2[1], v45 = wp2[2], v67 = wp2[3];
            acc[8]  = ffma2(aa, v01.x, acc[8]);
            acc[9]  = ffma2(aa, v01.y, acc[9]);
            acc[10] = ffma2(aa, v23.x, acc[10]);
            acc[11] = ffma2(aa, v23.y, acc[11]);
            acc[12] = ffma2(aa, v45.x, acc[12]);
            acc[13] = ffma2(aa, v45.y, acc[13]);
            acc[14] = ffma2(aa, v67.x, acc[14]);
            acc[15] = ffma2(aa, v67.y, acc[15]);
        }
    }

    if (cur_nt >= 0) {
        int gn = cur_nt * 128 + nloc;
#pragma unroll
        for (int q = 0; q < 16; q++) {
            atomicAdd(&out[gn * L_ + l0 + q], lo32(acc[q]));
            atomicAdd(&out[(gn + 1) * L_ + l0 + q], hi32(acc[q]));
        }
    }
}

// ---------------------------------------------------------------- launch
extern "C" void kernel_launch(void* const* d_in, const int* in_sizes, int n_in,
                              void* d_out, int out_size) {
    const float* feats = (const float*)d_in[0];
    const int*   pos   = (const int*)d_in[1];
    const int*   ht    = (const int*)d_in[2];
    const float* Wh    = (const float*)d_in[3];
    const float* bh    = (const float*)d_in[4];
    const float* Wt    = (const float*)d_in[5];
    const float* bt    = (const float*)d_in[6];
    const float* Wc    = (const float*)d_in[7];
    const float* bc    = (const float*)d_in[8];
    float*       out   = (float*)d_out;

    cudaFuncSetAttribute(bilinear_kernel,
                         cudaFuncAttributeMaxDynamicSharedMemorySize, K5_SMEM_BYTES);
    cudaFuncSetAttribute(l96_kernel,
                         cudaFuncAttributeMaxDynamicSharedMemorySize, L96_SMEM);

    build_ent_kernel<<<NENT, 192>>>(feats, pos);

    dim3 g2(NENT / 64, H_ / 128, 2);
    gemm_tanh_kernel<<<g2, 256>>>(Wh, bh, Wt, bt);

    init_out_kernel<<<(NROWS * L_ + 255) / 256, 256>>>(bc, out);

    dim3 g4(NROWS / 64, 12);
    l96_kernel<<<g4, 256, L96_SMEM>>>(ht, Wc, out);

    bilinear_kernel<<<NCTAS, 384, K5_SMEM_BYTES>>>(ht, Wc, out);
}

// round 6
// speedup vs baseline: 1.0312x; 1.0312x over previous
#include <cuda_runtime.h>
#include <cstdint>

// DocREDModel: entity-pool -> tanh-projection -> block-bilinear classifier
// B=16 S=2048 H=768 E=32 M=4 P=128 L=97 BLOCK=64
//
//  k1: ent (512x768) dedup-weighted gather-sum
//  k2: zh = tanh(ent@Wh+bh), zt = tanh(ent@Wt+bt)  (packed f32x2, dup-B)
//  k3: out = bc broadcast + queue reset
//  k4: l=96 column, grid (32 nt, 12 cb, 2 i-half)
//  k5: bilinear GEMM l=0..95: atomic work queue of 768 items
//      (16 nt x 12 cb x 4 sixteenths of ii).  Warp tile 128n x 8l, dup-pair Ws
//      broadcasts, REGISTER-PIPELINED Ws fill (prefetch next ii under the
//      inner loop), packed f32x2 FMA accumulation.

#define B_    16
#define S_    2048
#define H_    768
#define E_    32
#define L_    97
#define NROWS 2048
#define NENT  512

typedef unsigned long long ull;

__device__ float g_ent[NENT * H_];
__device__ float g_zh[NENT * H_];
__device__ float g_zt[NENT * H_];
__device__ int   g_qhead;

__device__ __forceinline__ ull ffma2(ull a, ull b, ull c) {
    ull d; asm("fma.rn.f32x2 %0, %1, %2, %3;" : "=l"(d) : "l"(a), "l"(b), "l"(c));
    return d;
}
__device__ __forceinline__ ull fmul2(ull a, ull b) {
    ull d; asm("mul.rn.f32x2 %0, %1, %2;" : "=l"(d) : "l"(a), "l"(b));
    return d;
}
__device__ __forceinline__ ull fsplat(float x) {
    ull d; asm("mov.b64 %0, {%1, %1};" : "=l"(d) : "f"(x));
    return d;
}
__device__ __forceinline__ float lo32(ull v) { return __uint_as_float((unsigned)(v & 0xffffffffull)); }
__device__ __forceinline__ float hi32(ull v) { return __uint_as_float((unsigned)(v >> 32)); }

// ---------------------------------------------------------------- kernel 1
__global__ void build_ent_kernel(const float* __restrict__ feats,
                                 const int* __restrict__ pos) {
    int be = blockIdx.x;
    int b  = be >> 5;
    const int* pp = pos + be * 4;
    int p0 = pp[0], p1 = pp[1], p2 = pp[2], p3 = pp[3];
    float w1 = (p1 != p0) ? 1.f : 0.f;
    float w2 = (p2 != p0 && p2 != p1) ? 1.f : 0.f;
    float w3 = (p3 != p0 && p3 != p1 && p3 != p2) ? 1.f : 0.f;
    const float* base = feats + (size_t)b * S_ * H_;
    const float4* r0 = (const float4*)(base + (size_t)p0 * H_);
    const float4* r1 = (const float4*)(base + (size_t)p1 * H_);
    const float4* r2 = (const float4*)(base + (size_t)p2 * H_);
    const float4* r3 = (const float4*)(base + (size_t)p3 * H_);
    int t = threadIdx.x;   // 192 threads * float4 = 768
    float4 v0 = r0[t], v1 = r1[t], v2 = r2[t], v3 = r3[t];
    float4 o;
    o.x = v0.x + w1 * v1.x + w2 * v2.x + w3 * v3.x;
    o.y = v0.y + w1 * v1.y + w2 * v2.y + w3 * v3.y;
    o.z = v0.z + w1 * v1.z + w2 * v2.z + w3 * v3.z;
    o.w = v0.w + w1 * v1.w + w2 * v2.w + w3 * v3.w;
    ((float4*)(g_ent + (size_t)be * H_))[t] = o;
}

// ---------------------------------------------------------------- kernel 2
__global__ void __launch_bounds__(256)
gemm_tanh_kernel(const float* __restrict__ Wh, const float* __restrict__ bh,
                 const float* __restrict__ Wt, const float* __restrict__ bt) {
    const float* W    = blockIdx.z ? Wt : Wh;
    const float* bias = blockIdx.z ? bt : bh;
    float*       Z    = blockIdx.z ? g_zt : g_zh;

    __shared__ float AsT[16 * 68];
    __shared__ float Bd[16 * 256];

    int tid = threadIdx.x;
    int mg  = tid & 15;
    int ng  = tid >> 4;
    int m0  = blockIdx.x * 64;
    int n0  = blockIdx.y * 128;

    ull acc[2][8];
#pragma unroll
    for (int p = 0; p < 2; p++)
#pragma unroll
        for (int c = 0; c < 8; c++) acc[p][c] = 0ull;

    for (int k0 = 0; k0 < H_; k0 += 16) {
        __syncthreads();
#pragma unroll
        for (int e = tid; e < 1024; e += 256) {
            int kk = e & 15, m = e >> 4;
            AsT[kk * 68 + m] = g_ent[(m0 + m) * H_ + k0 + kk];
        }
#pragma unroll
        for (int e = tid; e < 2048; e += 256) {
            int n = e & 127, kk = e >> 7;
            float w = W[(k0 + kk) * H_ + n0 + n];
            ((float2*)Bd)[kk * 128 + n] = make_float2(w, w);
        }
        __syncthreads();
#pragma unroll
        for (int kk = 0; kk < 16; kk++) {
            ulonglong2 av = *(const ulonglong2*)&AsT[kk * 68 + mg * 4];
            const ulonglong2* wp = (const ulonglong2*)&Bd[kk * 256 + ng * 16];
            ulonglong2 w01 = wp[0], w23 = wp[1], w45 = wp[2], w67 = wp[3];
            ull w[8] = {w01.x, w01.y, w23.x, w23.y, w45.x, w45.y, w67.x, w67.y};
#pragma unroll
            for (int c = 0; c < 8; c++) {
                acc[0][c] = ffma2(av.x, w[c], acc[0][c]);
                acc[1][c] = ffma2(av.y, w[c], acc[1][c]);
            }
        }
    }
#pragma unroll
    for (int p = 0; p < 2; p++) {
#pragma unroll
        for (int c = 0; c < 8; c++) {
            int n = n0 + ng * 8 + c;
            float bv = bias[n];
            int m = m0 + mg * 4 + 2 * p;
            Z[m * H_ + n]       = tanhf(lo32(acc[p][c]) + bv);
            Z[(m + 1) * H_ + n] = tanhf(hi32(acc[p][c]) + bv);
        }
    }
}

// ---------------------------------------------------------------- kernel 3
__global__ void init_out_kernel(const float* __restrict__ bc, float* __restrict__ out) {
    int i = blockIdx.x * blockDim.x + threadIdx.x;
    if (i == 0) g_qhead = 0;
    if (i < NROWS * L_) out[i] = bc[i % L_];
}

// ---------------------------------------------------------------- kernel 4
// l=96 column.  Grid (32 n-tiles of 64, 12 cb, 2 i-halves), 256 threads.
__global__ void __launch_bounds__(256)
l96_kernel(const int* __restrict__ ht, const float* __restrict__ Wc,
           float* __restrict__ out) {
    __shared__ float b1c[32 * 64];     // [i_local][n]
    __shared__ float b2c[64 * 64];     // [j][n]
    __shared__ float w96[2048];        // [i_local*64 + j]
    __shared__ int rh[64], rt[64];

    int tid = threadIdx.x;
    int nb  = blockIdx.x * 64;
    int cb  = blockIdx.y;
    int z   = blockIdx.z;              // i-half

    if (tid < 64) {
        int g = nb + tid;
        int b = g >> 7;
        rh[tid] = b * E_ + ht[2 * g];
        rt[tid] = b * E_ + ht[2 * g + 1];
    }
    __syncthreads();

    for (int e = tid; e < 2048; e += 256) {
        int n = e >> 5, i = e & 31;
        b1c[i * 64 + n] = g_zh[rh[n] * H_ + cb * 64 + z * 32 + i];
    }
    for (int e = tid; e < 4096; e += 256) {
        int n = e >> 6, j = e & 63;
        b2c[j * 64 + n] = g_zt[rt[n] * H_ + cb * 64 + j];
    }
    for (int e = tid; e < 2048; e += 256)
        w96[e] = Wc[(size_t)(cb * 4096 + z * 2048 + e) * L_ + 96];
    __syncthreads();

    int ngp  = tid & 15;
    int nloc = ngp * 4;
    int sl   = tid >> 4;               // 16 slices, 2 i-rows each
    ull acc0 = 0, acc1 = 0;

#pragma unroll
    for (int i2 = 0; i2 < 2; i2++) {
        int i = sl * 2 + i2;
        ulonglong2 b1p = *(const ulonglong2*)&b1c[i * 64 + nloc];
        const float* wr = &w96[i * 64];
#pragma unroll 8
        for (int j = 0; j < 64; j++) {
            ulonglong2 q = *(const ulonglong2*)&b2c[j * 64 + nloc];
            ull wp = fsplat(wr[j]);
            acc0 = ffma2(fmul2(q.x, b1p.x), wp, acc0);
            acc1 = ffma2(fmul2(q.y, b1p.y), wp, acc1);
        }
    }
    int n0 = nb + nloc;
    atomicAdd(&out[(n0 + 0) * L_ + 96], lo32(acc0));
    atomicAdd(&out[(n0 + 1) * L_ + 96], hi32(acc0));
    atomicAdd(&out[(n0 + 2) * L_ + 96], lo32(acc1));
    atomicAdd(&out[(n0 + 3) * L_ + 96], hi32(acc1));
}

// ---------------------------------------------------------------- kernel 5
// Bilinear GEMM l=0..95.  Queue of 768 items = 16 nt x 12 cb x 4 sixteenths.
// 384 thr = 12 warps: warp w -> l-block [8w, 8w+8); lane -> 4 n (2 f32x2 pairs).
// Per ii: Ws (64 Wc rows as dup pairs) STS'd from registers PREFETCHED during
// the previous ii's inner loop -> gmem latency fully hidden.

#define K5_B1_F  (16 * 128)
#define K5_B2_F  (64 * 128)
#define K5_WS_F  (64 * 192)
#define K5_SMEM_BYTES ((K5_B1_F + K5_B2_F + K5_WS_F) * 4 + 256 * 4)
#define N_ITEMS 768
#define NCTAS 296

__global__ void __launch_bounds__(384, 2)
bilinear_kernel(const int* __restrict__ ht, const float* __restrict__ Wc,
                float* __restrict__ out) {
    extern __shared__ float sm[];
    float* b1T = sm;                              // [16][128]
    float* b2T = sm + K5_B1_F;                    // [64][128]
    float* Wsd = sm + K5_B1_F + K5_B2_F;          // [64][96 dup pairs] stride 192
    int*   rh  = (int*)(sm + K5_B1_F + K5_B2_F + K5_WS_F);
    int*   rt  = rh + 128;
    __shared__ int s_item;

    int tid   = threadIdx.x;
    int warp  = tid >> 5;
    int lane  = tid & 31;
    int nloc  = lane * 4;
    int lq    = warp * 16;                        // float offset (8 dup pairs)
    int lfill = tid % 96;
    int jf0   = tid / 96;                         // 0..3

    for (;;) {
        __syncthreads();                          // prior item's smem reads done
        if (tid == 0) s_item = atomicAdd(&g_qhead, 1);
        __syncthreads();
        int item = s_item;
        if (item >= N_ITEMS) break;

        int nt   = item & 15;
        int rest = item >> 4;                     // 0..47
        int cb   = rest >> 2;
        int qq   = rest & 3;
        int col0 = cb * 64 + qq * 16;             // 16 ii starting here

        if (tid < 128) {
            int g = nt * 128 + tid;               // batch b == nt
            rh[tid] = nt * E_ + ht[2 * g];
            rt[tid] = nt * E_ + ht[2 * g + 1];
        }
        __syncthreads();

        for (int e = tid; e < 16 * 128; e += 384) {
            int i = e & 15, n = e >> 4;
            b1T[i * 128 + n] = g_zh[rh[n] * H_ + col0 + i];
        }
        for (int e = tid; e < 64 * 128; e += 384) {
            int j = e & 63, n = e >> 6;
            b2T[j * 128 + n] = g_zt[rt[n] * H_ + cb * 64 + j];
        }

        // prefetch Ws for ii=0
        float wreg[16];
        {
            const float* wc = Wc + (size_t)(col0 * 64 + jf0) * L_ + lfill;
#pragma unroll
            for (int s = 0; s < 16; s++) wreg[s] = wc[(size_t)(4 * s) * L_];
        }

        ull acc[2][8];
#pragma unroll
        for (int p = 0; p < 2; p++)
#pragma unroll
            for (int c = 0; c < 8; c++) acc[p][c] = 0ull;

        for (int ii = 0; ii < 16; ii++) {
            __syncthreads();                      // fills done / prior Wsd reads done
#pragma unroll
            for (int s = 0; s < 16; s++)
                ((float2*)Wsd)[(jf0 + 4 * s) * 96 + lfill] =
                    make_float2(wreg[s], wreg[s]);
            if (ii < 15) {                        // prefetch next ii (hidden by inner)
                const float* wc = Wc + (size_t)((col0 + ii + 1) * 64 + jf0) * L_ + lfill;
#pragma unroll
                for (int s = 0; s < 16; s++) wreg[s] = wc[(size_t)(4 * s) * L_];
            }
            __syncthreads();                      // Wsd ready

            ulonglong2 b1p = *(const ulonglong2*)(b1T + ii * 128 + nloc);

#pragma unroll 4
            for (int j = 0; j < 64; j++) {
                ulonglong2 q = *(const ulonglong2*)(b2T + j * 128 + nloc);
                ull a0 = fmul2(q.x, b1p.x);
                ull a1 = fmul2(q.y, b1p.y);
                const ulonglong2* wp = (const ulonglong2*)(Wsd + j * 192 + lq);
                ulonglong2 w01 = wp[0], w23 = wp[1], w45 = wp[2], w67 = wp[3];
                acc[0][0] = ffma2(a0, w01.x, acc[0][0]);
                acc[1][0] = ffma2(a1, w01.x, acc[1][0]);
                acc[0][1] = ffma2(a0, w01.y, acc[0][1]);
                acc[1][1] = ffma2(a1, w01.y, acc[1][1]);
                acc[0][2] = ffma2(a0, w23.x, acc[0][2]);
                acc[1][2] = ffma2(a1, w23.x, acc[1][2]);
                acc[0][3] = ffma2(a0, w23.y, acc[0][3]);
                acc[1][3] = ffma2(a1, w23.y, acc[1][3]);
                acc[0][4] = ffma2(a0, w45.x, acc[0][4]);
                acc[1][4] = ffma2(a1, w45.x, acc[1][4]);
                acc[0][5] = ffma2(a0, w45.y, acc[0][5]);
                acc[1][5] = ffma2(a1, w45.y, acc[1][5]);
                acc[0][6] = ffma2(a0, w67.x, acc[0][6]);
                acc[1][6] = ffma2(a1, w67.x, acc[1][6]);
                acc[0][7] = ffma2(a0, w67.y, acc[0][7]);
                acc[1][7] = ffma2(a1, w67.y, acc[1][7]);
            }
        }

        int l0  = warp * 8;
        int nb0 = nt * 128 + nloc;
#pragma unroll
        for (int c = 0; c < 8; c++) {
            int l = l0 + c;
            atomicAdd(&out[(nb0 + 0) * L_ + l], lo32(acc[0][c]));
            atomicAdd(&out[(nb0 + 1) * L_ + l], hi32(acc[0][c]));
            atomicAdd(&out[(nb0 + 2) * L_ + l], lo32(acc[1][c]));
            atomicAdd(&out[(nb0 + 3) * L_ + l], hi32(acc[1][c]));
        }
    }
}

// ---------------------------------------------------------------- launch
extern "C" void kernel_launch(void* const* d_in, const int* in_sizes, int n_in,
                              void* d_out, int out_size) {
    const float* feats = (const float*)d_in[0];
    const int*   pos   = (const int*)d_in[1];
    const int*   ht    = (const int*)d_in[2];
    const float* Wh    = (const float*)d_in[3];
    const float* bh    = (const float*)d_in[4];
    const float* Wt    = (const float*)d_in[5];
    const float* bt    = (const float*)d_in[6];
    const float* Wc    = (const float*)d_in[7];
    const float* bc    = (const float*)d_in[8];
    float*       out   = (float*)d_out;

    cudaFuncSetAttribute(bilinear_kernel,
                         cudaFuncAttributeMaxDynamicSharedMemorySize, K5_SMEM_BYTES);

    build_ent_kernel<<<NENT, 192>>>(feats, pos);

    dim3 g2(NENT / 64, H_ / 128, 2);
    gemm_tanh_kernel<<<g2, 256>>>(Wh, bh, Wt, bt);

    init_out_kernel<<<(NROWS * L_ + 255) / 256, 256>>>(bc, out);

    dim3 g4(NROWS / 64, 12, 2);
    l96_kernel<<<g4, 256>>>(ht, Wc, out);

    bilinear_kernel<<<NCTAS, 384, K5_SMEM_BYTES>>>(ht, Wc, out);
}

// round 7
// speedup vs baseline: 1.2599x; 1.2218x over previous
#include <cuda_runtime.h>
#include <cstdint>

// DocREDModel: entity-pool -> tanh-projection -> block-bilinear classifier
// B=16 S=2048 H=768 E=32 M=4 P=128 L=97 BLOCK=64
//
//  k1: ent (512x768) dedup-weighted gather-sum
//  k2: zh = tanh(ent@Wh+bh), zt = tanh(ent@Wt+bt)  (packed f32x2, dup-B)
//  k3: out = bc broadcast + queue reset
//  k3b: g_w96[k] = Wc[k][96]  (dense copy of the strided 97th column)
//  k4: l=96 column using dense g_w96
//  k5: bilinear GEMM l=0..95, queue of 768 items (16 nt x 12 cb x 4 q).
//      Warp tile 64n x 16l (2 n-halves x 6 l-blocks), lane owns 2 n.
//      l-PACKED f32x2 accumulators, plain (non-dup) Ws broadcasts,
//      register-prefetched Ws fill.  Crossbar traffic: 6 cyc / 1024 MACs.

#define B_    16
#define S_    2048
#define H_    768
#define E_    32
#define L_    97
#define NROWS 2048
#define NENT  512
#define KTOT  49152

typedef unsigned long long ull;

__device__ float g_ent[NENT * H_];
__device__ float g_zh[NENT * H_];
__device__ float g_zt[NENT * H_];
__device__ float g_w96[KTOT];
__device__ int   g_qhead;

__device__ __forceinline__ ull ffma2(ull a, ull b, ull c) {
    ull d; asm("fma.rn.f32x2 %0, %1, %2, %3;" : "=l"(d) : "l"(a), "l"(b), "l"(c));
    return d;
}
__device__ __forceinline__ ull fmul2(ull a, ull b) {
    ull d; asm("mul.rn.f32x2 %0, %1, %2;" : "=l"(d) : "l"(a), "l"(b));
    return d;
}
__device__ __forceinline__ ull fsplat(float x) {
    ull d; asm("mov.b64 %0, {%1, %1};" : "=l"(d) : "f"(x));
    return d;
}
__device__ __forceinline__ float lo32(ull v) { return __uint_as_float((unsigned)(v & 0xffffffffull)); }
__device__ __forceinline__ float hi32(ull v) { return __uint_as_float((unsigned)(v >> 32)); }

// ---------------------------------------------------------------- kernel 1
__global__ void build_ent_kernel(const float* __restrict__ feats,
                                 const int* __restrict__ pos) {
    int be = blockIdx.x;
    int b  = be >> 5;
    const int* pp = pos + be * 4;
    int p0 = pp[0], p1 = pp[1], p2 = pp[2], p3 = pp[3];
    float w1 = (p1 != p0) ? 1.f : 0.f;
    float w2 = (p2 != p0 && p2 != p1) ? 1.f : 0.f;
    float w3 = (p3 != p0 && p3 != p1 && p3 != p2) ? 1.f : 0.f;
    const float* base = feats + (size_t)b * S_ * H_;
    const float4* r0 = (const float4*)(base + (size_t)p0 * H_);
    const float4* r1 = (const float4*)(base + (size_t)p1 * H_);
    const float4* r2 = (const float4*)(base + (size_t)p2 * H_);
    const float4* r3 = (const float4*)(base + (size_t)p3 * H_);
    int t = threadIdx.x;   // 192 threads * float4 = 768
    float4 v0 = r0[t], v1 = r1[t], v2 = r2[t], v3 = r3[t];
    float4 o;
    o.x = v0.x + w1 * v1.x + w2 * v2.x + w3 * v3.x;
    o.y = v0.y + w1 * v1.y + w2 * v2.y + w3 * v3.y;
    o.z = v0.z + w1 * v1.z + w2 * v2.z + w3 * v3.z;
    o.w = v0.w + w1 * v1.w + w2 * v2.w + w3 * v3.w;
    ((float4*)(g_ent + (size_t)be * H_))[t] = o;
}

// ---------------------------------------------------------------- kernel 2
__global__ void __launch_bounds__(256)
gemm_tanh_kernel(const float* __restrict__ Wh, const float* __restrict__ bh,
                 const float* __restrict__ Wt, const float* __restrict__ bt) {
    const float* W    = blockIdx.z ? Wt : Wh;
    const float* bias = blockIdx.z ? bt : bh;
    float*       Z    = blockIdx.z ? g_zt : g_zh;

    __shared__ float AsT[16 * 68];
    __shared__ float Bd[16 * 256];

    int tid = threadIdx.x;
    int mg  = tid & 15;
    int ng  = tid >> 4;
    int m0  = blockIdx.x * 64;
    int n0  = blockIdx.y * 128;

    ull acc[2][8];
#pragma unroll
    for (int p = 0; p < 2; p++)
#pragma unroll
        for (int c = 0; c < 8; c++) acc[p][c] = 0ull;

    for (int k0 = 0; k0 < H_; k0 += 16) {
        __syncthreads();
#pragma unroll
        for (int e = tid; e < 1024; e += 256) {
            int kk = e & 15, m = e >> 4;
            AsT[kk * 68 + m] = g_ent[(m0 + m) * H_ + k0 + kk];
        }
#pragma unroll
        for (int e = tid; e < 2048; e += 256) {
            int n = e & 127, kk = e >> 7;
            float w = W[(k0 + kk) * H_ + n0 + n];
            ((float2*)Bd)[kk * 128 + n] = make_float2(w, w);
        }
        __syncthreads();
#pragma unroll
        for (int kk = 0; kk < 16; kk++) {
            ulonglong2 av = *(const ulonglong2*)&AsT[kk * 68 + mg * 4];
            const ulonglong2* wp = (const ulonglong2*)&Bd[kk * 256 + ng * 16];
            ulonglong2 w01 = wp[0], w23 = wp[1], w45 = wp[2], w67 = wp[3];
            ull w[8] = {w01.x, w01.y, w23.x, w23.y, w45.x, w45.y, w67.x, w67.y};
#pragma unroll
            for (int c = 0; c < 8; c++) {
                acc[0][c] = ffma2(av.x, w[c], acc[0][c]);
                acc[1][c] = ffma2(av.y, w[c], acc[1][c]);
            }
        }
    }
#pragma unroll
    for (int p = 0; p < 2; p++) {
#pragma unroll
        for (int c = 0; c < 8; c++) {
            int n = n0 + ng * 8 + c;
            float bv = bias[n];
            int m = m0 + mg * 4 + 2 * p;
            Z[m * H_ + n]       = tanhf(lo32(acc[p][c]) + bv);
            Z[(m + 1) * H_ + n] = tanhf(hi32(acc[p][c]) + bv);
        }
    }
}

// ---------------------------------------------------------------- kernel 3
__global__ void init_out_kernel(const float* __restrict__ bc, float* __restrict__ out) {
    int i = blockIdx.x * blockDim.x + threadIdx.x;
    if (i == 0) g_qhead = 0;
    if (i < NROWS * L_) out[i] = bc[i % L_];
}

// ---------------------------------------------------------------- kernel 3b
__global__ void w96_extract_kernel(const float* __restrict__ Wc) {
    int k = blockIdx.x * blockDim.x + threadIdx.x;
    if (k < KTOT) g_w96[k] = Wc[(size_t)k * L_ + 96];
}

// ---------------------------------------------------------------- kernel 4
// l=96 column.  Grid (32 n-tiles of 64, 12 cb), 256 threads, dense g_w96.
__global__ void __launch_bounds__(256)
l96_kernel(const int* __restrict__ ht, float* __restrict__ out) {
    __shared__ float b1c[64 * 64];     // [i][n]
    __shared__ float b2c[64 * 64];     // [j][n]
    __shared__ float w96[4096];
    __shared__ int rh[64], rt[64];

    int tid = threadIdx.x;
    int nb  = blockIdx.x * 64;
    int cb  = blockIdx.y;

    if (tid < 64) {
        int g = nb + tid;
        int b = g >> 7;
        rh[tid] = b * E_ + ht[2 * g];
        rt[tid] = b * E_ + ht[2 * g + 1];
    }
    __syncthreads();

    for (int e = tid; e < 4096; e += 256) {
        int n = e >> 6, i = e & 63;
        b1c[i * 64 + n] = g_zh[rh[n] * H_ + cb * 64 + i];
        b2c[i * 64 + n] = g_zt[rt[n] * H_ + cb * 64 + i];
    }
    for (int e = tid; e < 1024; e += 256)
        ((float4*)w96)[e] = ((const float4*)(g_w96 + cb * 4096))[e];
    __syncthreads();

    int ngp  = tid & 15;
    int nloc = ngp * 4;
    int i0   = (tid >> 4) * 4;         // 16 slices x 4 i-rows
    ull acc0 = 0, acc1 = 0;

#pragma unroll
    for (int i2 = 0; i2 < 4; i2++) {
        int i = i0 + i2;
        ulonglong2 b1p = *(const ulonglong2*)&b1c[i * 64 + nloc];
        const float* wr = &w96[i * 64];
#pragma unroll 8
        for (int j = 0; j < 64; j++) {
            ulonglong2 q = *(const ulonglong2*)&b2c[j * 64 + nloc];
            ull wp = fsplat(wr[j]);
            acc0 = ffma2(fmul2(q.x, b1p.x), wp, acc0);
            acc1 = ffma2(fmul2(q.y, b1p.y), wp, acc1);
        }
    }
    int n0 = nb + nloc;
    atomicAdd(&out[(n0 + 0) * L_ + 96], lo32(acc0));
    atomicAdd(&out[(n0 + 1) * L_ + 96], hi32(acc0));
    atomicAdd(&out[(n0 + 2) * L_ + 96], lo32(acc1));
    atomicAdd(&out[(n0 + 3) * L_ + 96], hi32(acc1));
}

// ---------------------------------------------------------------- kernel 5
// Bilinear GEMM l=0..95.  Queue of 768 items = 16 nt x 12 cb x 4 quarters.
// 384 thr = 12 warps: warp w -> l-block (w%6)*16, n-half (w/6)*64.
// Lane owns 2 n.  Accumulators l-packed (f32x2 over adjacent l).
// Ws: plain floats [64][96] (broadcast reads), register-prefetched.

#define K5_B1_F  (16 * 128)
#define K5_B2_F  (64 * 128)
#define K5_WS_F  (64 * 96)
#define K5_SMEM_BYTES ((K5_B1_F + K5_B2_F + K5_WS_F) * 4 + 256 * 4)
#define N_ITEMS 768
#define NCTAS 296

__global__ void __launch_bounds__(384, 2)
bilinear_kernel(const int* __restrict__ ht, const float* __restrict__ Wc,
                float* __restrict__ out) {
    extern __shared__ float sm[];
    float* b1T = sm;                              // [16][128]
    float* b2T = sm + K5_B1_F;                    // [64][128]
    float* Wsd = sm + K5_B1_F + K5_B2_F;          // [64][96] plain
    int*   rh  = (int*)(sm + K5_B1_F + K5_B2_F + K5_WS_F);
    int*   rt  = rh + 128;
    __shared__ int s_item;

    int tid   = threadIdx.x;
    int warp  = tid >> 5;
    int lane  = tid & 31;
    int lblk  = warp % 6;
    int nh    = warp / 6;
    int l0    = lblk * 16;
    int nloc  = nh * 64 + lane * 2;               // lane's n pair
    int lfill = tid % 96;
    int jf0   = tid / 96;                         // 0..3

    for (;;) {
        __syncthreads();                          // prior item's smem reads done
        if (tid == 0) s_item = atomicAdd(&g_qhead, 1);
        __syncthreads();
        int item = s_item;
        if (item >= N_ITEMS) break;

        int nt   = item & 15;
        int rest = item >> 4;                     // 0..47
        int cb   = rest >> 2;
        int qq   = rest & 3;
        int col0 = cb * 64 + qq * 16;             // 16 ii starting here

        if (tid < 128) {
            int g = nt * 128 + tid;               // batch b == nt
            rh[tid] = nt * E_ + ht[2 * g];
            rt[tid] = nt * E_ + ht[2 * g + 1];
        }
        __syncthreads();

        for (int e = tid; e < 16 * 128; e += 384) {
            int i = e & 15, n = e >> 4;
            b1T[i * 128 + n] = g_zh[rh[n] * H_ + col0 + i];
        }
        for (int e = tid; e < 64 * 128; e += 384) {
            int j = e & 63, n = e >> 6;
            b2T[j * 128 + n] = g_zt[rt[n] * H_ + cb * 64 + j];
        }

        // prefetch Ws for ii=0
        float wreg[16];
        {
            const float* wc = Wc + (size_t)(col0 * 64 + jf0) * L_ + lfill;
#pragma unroll
            for (int s = 0; s < 16; s++) wreg[s] = wc[(size_t)(4 * s) * L_];
        }

        ull acc[2][8];
#pragma unroll
        for (int p = 0; p < 2; p++)
#pragma unroll
            for (int c = 0; c < 8; c++) acc[p][c] = 0ull;

        for (int ii = 0; ii < 16; ii++) {
            __syncthreads();                      // fills done / prior Wsd reads done
#pragma unroll
            for (int s = 0; s < 16; s++)
                Wsd[(jf0 + 4 * s) * 96 + lfill] = wreg[s];
            if (ii < 15) {                        // prefetch next ii under inner loop
                const float* wc = Wc + (size_t)((col0 + ii + 1) * 64 + jf0) * L_ + lfill;
#pragma unroll
                for (int s = 0; s < 16; s++) wreg[s] = wc[(size_t)(4 * s) * L_];
            }
            __syncthreads();                      // Wsd ready

            ull b1p = *(const ull*)(b1T + ii * 128 + nloc);

#pragma unroll 4
            for (int j = 0; j < 64; j++) {
                ull q  = *(const ull*)(b2T + j * 128 + nloc);
                ull ap = fmul2(q, b1p);           // (a_n0, a_n1)
                ull s0 = fsplat(lo32(ap));
                ull s1 = fsplat(hi32(ap));
                const ulonglong2* wp = (const ulonglong2*)(Wsd + j * 96 + l0);
                ulonglong2 w01 = wp[0], w23 = wp[1], w45 = wp[2], w67 = wp[3];
                acc[0][0] = ffma2(s0, w01.x, acc[0][0]);
                acc[1][0] = ffma2(s1, w01.x, acc[1][0]);
                acc[0][1] = ffma2(s0, w01.y, acc[0][1]);
                acc[1][1] = ffma2(s1, w01.y, acc[1][1]);
                acc[0][2] = ffma2(s0, w23.x, acc[0][2]);
                acc[1][2] = ffma2(s1, w23.x, acc[1][2]);
                acc[0][3] = ffma2(s0, w23.y, acc[0][3]);
                acc[1][3] = ffma2(s1, w23.y, acc[1][3]);
                acc[0][4] = ffma2(s0, w45.x, acc[0][4]);
                acc[1][4] = ffma2(s1, w45.x, acc[1][4]);
                acc[0][5] = ffma2(s0, w45.y, acc[0][5]);
                acc[1][5] = ffma2(s1, w45.y, acc[1][5]);
                acc[0][6] = ffma2(s0, w67.x, acc[0][6]);
                acc[1][6] = ffma2(s1, w67.x, acc[1][6]);
                acc[0][7] = ffma2(s0, w67.y, acc[0][7]);
                acc[1][7] = ffma2(s1, w67.y, acc[1][7]);
            }
        }

        int nb0 = nt * 128 + nloc;
#pragma unroll
        for (int nn = 0; nn < 2; nn++) {
            float* orow = out + (size_t)(nb0 + nn) * L_ + l0;
#pragma unroll
            for (int p = 0; p < 8; p++) {
                atomicAdd(orow + 2 * p,     lo32(acc[nn][p]));
                atomicAdd(orow + 2 * p + 1, hi32(acc[nn][p]));
            }
        }
    }
}

// ---------------------------------------------------------------- launch
extern "C" void kernel_launch(void* const* d_in, const int* in_sizes, int n_in,
                              void* d_out, int out_size) {
    const float* feats = (const float*)d_in[0];
    const int*   pos   = (const int*)d_in[1];
    const int*   ht    = (const int*)d_in[2];
    const float* Wh    = (const float*)d_in[3];
    const float* bh    = (const float*)d_in[4];
    const float* Wt    = (const float*)d_in[5];
    const float* bt    = (const float*)d_in[6];
    const float* Wc    = (const float*)d_in[7];
    const float* bc    = (const float*)d_in[8];
    float*       out   = (float*)d_out;

    cudaFuncSetAttribute(bilinear_kernel,
                         cudaFuncAttributeMaxDynamicSharedMemorySize, K5_SMEM_BYTES);

    build_ent_kernel<<<NENT, 192>>>(feats, pos);

    dim3 g2(NENT / 64, H_ / 128, 2);
    gemm_tanh_kernel<<<g2, 256>>>(Wh, bh, Wt, bt);

    init_out_kernel<<<(NROWS * L_ + 255) / 256, 256>>>(bc, out);
    w96_extract_kernel<<<(KTOT + 255) / 256, 256>>>(Wc);

    dim3 g4(NROWS / 64, 12);
    l96_kernel<<<g4, 256>>>(ht, out);

    bilinear_kernel<<<NCTAS, 384, K5_SMEM_BYTES>>>(ht, Wc, out);
}

// round 8
// speedup vs baseline: 1.8763x; 1.4893x over previous
#include <cuda_runtime.h>
#include <cstdint>

// DocREDModel: entity-pool -> tanh-projection -> block-bilinear classifier
// B=16 S=2048 H=768 E=32 M=4 P=128 L=97 BLOCK=64
//
// Algebraic factorization (4x FLOP cut over direct bilinear GEMM):
//   C[e2, cb*64+i, l] = sum_j zt[e2, cb*64+j] * Wc[(cb*64+i)*64+j, l]   (4.8 GF)
//   D[b, e1, e2, l]   = sum_k1 zh[b*32+e1, k1] * C[b*32+e2, k1, l]      (2.4 GF)
//   logits[n, l]      = D[b, ht[n,0], ht[n,1], l] + bc[l]               (gather)
// l=96 column handled by a dedicated small path (dense w96 copy).

#define B_    16
#define S_    2048
#define H_    768
#define E_    32
#define L_    97
#define CH    96
#define NROWS 2048
#define NENT  512
#define KTOT  49152

typedef unsigned long long ull;

__device__ float g_ent[NENT * H_];
__device__ float g_zh[NENT * H_];
__device__ float g_zt[NENT * H_];
__device__ float g_w96[KTOT];
__device__ float g_C[(size_t)NENT * H_ * CH];      // 512*768*96 = 151 MB scratch
__device__ float g_D[B_ * E_ * E_ * CH];           // 6.3 MB

__device__ __forceinline__ ull ffma2(ull a, ull b, ull c) {
    ull d; asm("fma.rn.f32x2 %0, %1, %2, %3;" : "=l"(d) : "l"(a), "l"(b), "l"(c));
    return d;
}
__device__ __forceinline__ ull fmul2(ull a, ull b) {
    ull d; asm("mul.rn.f32x2 %0, %1, %2;" : "=l"(d) : "l"(a), "l"(b));
    return d;
}
__device__ __forceinline__ ull fsplat(float x) {
    ull d; asm("mov.b64 %0, {%1, %1};" : "=l"(d) : "f"(x));
    return d;
}
__device__ __forceinline__ float lo32(ull v) { return __uint_as_float((unsigned)(v & 0xffffffffull)); }
__device__ __forceinline__ float hi32(ull v) { return __uint_as_float((unsigned)(v >> 32)); }

// ---------------------------------------------------------------- kernel 1
__global__ void build_ent_kernel(const float* __restrict__ feats,
                                 const int* __restrict__ pos) {
    int be = blockIdx.x;
    int b  = be >> 5;
    const int* pp = pos + be * 4;
    int p0 = pp[0], p1 = pp[1], p2 = pp[2], p3 = pp[3];
    float w1 = (p1 != p0) ? 1.f : 0.f;
    float w2 = (p2 != p0 && p2 != p1) ? 1.f : 0.f;
    float w3 = (p3 != p0 && p3 != p1 && p3 != p2) ? 1.f : 0.f;
    const float* base = feats + (size_t)b * S_ * H_;
    const float4* r0 = (const float4*)(base + (size_t)p0 * H_);
    const float4* r1 = (const float4*)(base + (size_t)p1 * H_);
    const float4* r2 = (const float4*)(base + (size_t)p2 * H_);
    const float4* r3 = (const float4*)(base + (size_t)p3 * H_);
    int t = threadIdx.x;   // 192 threads * float4 = 768
    float4 v0 = r0[t], v1 = r1[t], v2 = r2[t], v3 = r3[t];
    float4 o;
    o.x = v0.x + w1 * v1.x + w2 * v2.x + w3 * v3.x;
    o.y = v0.y + w1 * v1.y + w2 * v2.y + w3 * v3.y;
    o.z = v0.z + w1 * v1.z + w2 * v2.z + w3 * v3.z;
    o.w = v0.w + w1 * v1.w + w2 * v2.w + w3 * v3.w;
    ((float4*)(g_ent + (size_t)be * H_))[t] = o;
}

// ---------------------------------------------------------------- kernel 2
__global__ void __launch_bounds__(256)
gemm_tanh_kernel(const float* __restrict__ Wh, const float* __restrict__ bh,
                 const float* __restrict__ Wt, const float* __restrict__ bt) {
    const float* W    = blockIdx.z ? Wt : Wh;
    const float* bias = blockIdx.z ? bt : bh;
    float*       Z    = blockIdx.z ? g_zt : g_zh;

    __shared__ float AsT[16 * 68];
    __shared__ float Bd[16 * 256];

    int tid = threadIdx.x;
    int mg  = tid & 15;
    int ng  = tid >> 4;
    int m0  = blockIdx.x * 64;
    int n0  = blockIdx.y * 128;

    ull acc[2][8];
#pragma unroll
    for (int p = 0; p < 2; p++)
#pragma unroll
        for (int c = 0; c < 8; c++) acc[p][c] = 0ull;

    for (int k0 = 0; k0 < H_; k0 += 16) {
        __syncthreads();
#pragma unroll
        for (int e = tid; e < 1024; e += 256) {
            int kk = e & 15, m = e >> 4;
            AsT[kk * 68 + m] = g_ent[(m0 + m) * H_ + k0 + kk];
        }
#pragma unroll
        for (int e = tid; e < 2048; e += 256) {
            int n = e & 127, kk = e >> 7;
            float w = W[(k0 + kk) * H_ + n0 + n];
            ((float2*)Bd)[kk * 128 + n] = make_float2(w, w);
        }
        __syncthreads();
#pragma unroll
        for (int kk = 0; kk < 16; kk++) {
            ulonglong2 av = *(const ulonglong2*)&AsT[kk * 68 + mg * 4];
            const ulonglong2* wp = (const ulonglong2*)&Bd[kk * 256 + ng * 16];
            ulonglong2 w01 = wp[0], w23 = wp[1], w45 = wp[2], w67 = wp[3];
            ull w[8] = {w01.x, w01.y, w23.x, w23.y, w45.x, w45.y, w67.x, w67.y};
#pragma unroll
            for (int c = 0; c < 8; c++) {
                acc[0][c] = ffma2(av.x, w[c], acc[0][c]);
                acc[1][c] = ffma2(av.y, w[c], acc[1][c]);
            }
        }
    }
#pragma unroll
    for (int p = 0; p < 2; p++) {
#pragma unroll
        for (int c = 0; c < 8; c++) {
            int n = n0 + ng * 8 + c;
            float bv = bias[n];
            int m = m0 + mg * 4 + 2 * p;
            Z[m * H_ + n]       = tanhf(lo32(acc[p][c]) + bv);
            Z[(m + 1) * H_ + n] = tanhf(hi32(acc[p][c]) + bv);
        }
    }
}

// ---------------------------------------------------------------- kernel 3
__global__ void init_out_kernel(const float* __restrict__ bc, float* __restrict__ out) {
    int i = blockIdx.x * blockDim.x + threadIdx.x;
    if (i < NROWS * L_) out[i] = bc[i % L_];
}

// ---------------------------------------------------------------- kernel 3b
__global__ void w96_extract_kernel(const float* __restrict__ Wc) {
    int k = blockIdx.x * blockDim.x + threadIdx.x;
    if (k < KTOT) g_w96[k] = Wc[(size_t)k * L_ + 96];
}

// ---------------------------------------------------------------- kernel 4
// l=96 column.  Grid (32 n-tiles of 64, 12 cb), 256 threads, dense g_w96.
__global__ void __launch_bounds__(256)
l96_kernel(const int* __restrict__ ht, float* __restrict__ out) {
    __shared__ float b1c[64 * 64];     // [i][n]
    __shared__ float b2c[64 * 64];     // [j][n]
    __shared__ float w96[4096];
    __shared__ int rh[64], rt[64];

    int tid = threadIdx.x;
    int nb  = blockIdx.x * 64;
    int cb  = blockIdx.y;

    if (tid < 64) {
        int g = nb + tid;
        int b = g >> 7;
        rh[tid] = b * E_ + ht[2 * g];
        rt[tid] = b * E_ + ht[2 * g + 1];
    }
    __syncthreads();

    for (int e = tid; e < 4096; e += 256) {
        int n = e >> 6, i = e & 63;
        b1c[i * 64 + n] = g_zh[rh[n] * H_ + cb * 64 + i];
        b2c[i * 64 + n] = g_zt[rt[n] * H_ + cb * 64 + i];
    }
    for (int e = tid; e < 1024; e += 256)
        ((float4*)w96)[e] = ((const float4*)(g_w96 + cb * 4096))[e];
    __syncthreads();

    int ngp  = tid & 15;
    int nloc = ngp * 4;
    int i0   = (tid >> 4) * 4;
    ull acc0 = 0, acc1 = 0;

#pragma unroll
    for (int i2 = 0; i2 < 4; i2++) {
        int i = i0 + i2;
        ulonglong2 b1p = *(const ulonglong2*)&b1c[i * 64 + nloc];
        const float* wr = &w96[i * 64];
#pragma unroll 8
        for (int j = 0; j < 64; j++) {
            ulonglong2 q = *(const ulonglong2*)&b2c[j * 64 + nloc];
            ull wp = fsplat(wr[j]);
            acc0 = ffma2(fmul2(q.x, b1p.x), wp, acc0);
            acc1 = ffma2(fmul2(q.y, b1p.y), wp, acc1);
        }
    }
    int n0 = nb + nloc;
    atomicAdd(&out[(n0 + 0) * L_ + 96], lo32(acc0));
    atomicAdd(&out[(n0 + 1) * L_ + 96], hi32(acc0));
    atomicAdd(&out[(n0 + 2) * L_ + 96], lo32(acc1));
    atomicAdd(&out[(n0 + 3) * L_ + 96], hi32(acc1));
}

// ---------------------------------------------------------------- stage 1
// C[e2, cb*64+i, l] = sum_j zt[e2, cb*64+j] * Wc[((cb*64+i)*64+j)*97 + l]
// Grid (12 cb, 8 e2-tiles of 64, 32 il-tiles of 2i x 96l), 256 threads.
// Thread: mg=tid&15 -> 4 e2 rows; ng=tid>>4 -> (i_loc, 12 l as 6 f32x2 pairs).
__global__ void __launch_bounds__(256, 3)
stage1_kernel(const float* __restrict__ Wc) {
    __shared__ float As[64 * 68];      // [j][e2_loc], stride 68
    __shared__ float Bs[64 * 192];     // [j][i_loc*96 + l]

    int tid = threadIdx.x;
    int cb  = blockIdx.x;
    int e0  = blockIdx.y * 64;
    int i0  = blockIdx.z * 2;          // i within cb block

    for (int e = tid; e < 4096; e += 256) {
        int j = e & 63, m = e >> 6;
        As[j * 68 + m] = g_zt[(e0 + m) * H_ + cb * 64 + j];
    }
    for (int e = tid; e < 12288; e += 256) {
        int row = e / 96, l = e - row * 96;     // row = i_loc*64 + j
        int il = row >> 6, j = row & 63;
        Bs[j * 192 + il * 96 + l] =
            Wc[(size_t)((cb * 64 + i0 + il) * 64 + j) * L_ + l];
    }
    __syncthreads();

    int mg = tid & 15;
    int ng = tid >> 4;
    int il = ng >> 3;
    int l0 = (ng & 7) * 12;
    const float* bptr = Bs + il * 96 + l0;
    const float* aptr = As + mg * 4;

    ull acc[4][6];
#pragma unroll
    for (int m = 0; m < 4; m++)
#pragma unroll
        for (int p = 0; p < 6; p++) acc[m][p] = 0ull;

#pragma unroll 4
    for (int k = 0; k < 64; k++) {
        float4 a = *(const float4*)(aptr + k * 68);
        ulonglong2 b01 = *(const ulonglong2*)(bptr + k * 192);
        ulonglong2 b23 = *(const ulonglong2*)(bptr + k * 192 + 4);
        ulonglong2 b45 = *(const ulonglong2*)(bptr + k * 192 + 8);
        ull bv[6] = {b01.x, b01.y, b23.x, b23.y, b45.x, b45.y};
        ull s0 = fsplat(a.x), s1 = fsplat(a.y), s2 = fsplat(a.z), s3 = fsplat(a.w);
#pragma unroll
        for (int p = 0; p < 6; p++) {
            acc[0][p] = ffma2(s0, bv[p], acc[0][p]);
            acc[1][p] = ffma2(s1, bv[p], acc[1][p]);
            acc[2][p] = ffma2(s2, bv[p], acc[2][p]);
            acc[3][p] = ffma2(s3, bv[p], acc[3][p]);
        }
    }

    int k1 = cb * 64 + i0 + il;
#pragma unroll
    for (int m = 0; m < 4; m++) {
        float* cptr = g_C + ((size_t)(e0 + mg * 4 + m) * H_ + k1) * CH + l0;
#pragma unroll
        for (int p = 0; p < 6; p++) *(ull*)(cptr + 2 * p) = acc[m][p];
    }
}

// ---------------------------------------------------------------- stage 2
// D[b, e1, e2, l] = sum_k1 zh[b*32+e1, k1] * C[b*32+e2, k1, l]
// Grid (16 b, 32 e2), 128 threads: mg=tid&15 -> 2 e1; ng=tid>>4 -> 12 l (6 pairs).
__global__ void __launch_bounds__(128)
stage2_kernel() {
    __shared__ float As[64 * 36];      // [kk][e1], stride 36
    __shared__ float Bs[64 * 96];      // [kk][l]

    int tid = threadIdx.x;
    int b   = blockIdx.x;
    int e2  = blockIdx.y;
    const float* crow = g_C + (size_t)(b * E_ + e2) * H_ * CH;

    int mg = tid & 15;
    int ng = tid >> 4;
    int l0 = ng * 12;

    ull acc[2][6];
#pragma unroll
    for (int m = 0; m < 2; m++)
#pragma unroll
        for (int p = 0; p < 6; p++) acc[m][p] = 0ull;

    for (int kc = 0; kc < 12; kc++) {
        __syncthreads();
        for (int e = tid; e < 2048; e += 128) {
            int kk = e & 63, e1 = e >> 6;
            As[kk * 36 + e1] = g_zh[(b * E_ + e1) * H_ + kc * 64 + kk];
        }
        for (int e = tid; e < 1536; e += 128)
            ((float4*)Bs)[e] = ((const float4*)(crow + kc * 64 * CH))[e];
        __syncthreads();

#pragma unroll 4
        for (int k = 0; k < 64; k++) {
            float2 a = *(const float2*)&As[k * 36 + mg * 2];
            ulonglong2 b01 = *(const ulonglong2*)&Bs[k * 96 + l0];
            ulonglong2 b23 = *(const ulonglong2*)&Bs[k * 96 + l0 + 4];
            ulonglong2 b45 = *(const ulonglong2*)&Bs[k * 96 + l0 + 8];
            ull bv[6] = {b01.x, b01.y, b23.x, b23.y, b45.x, b45.y};
            ull s0 = fsplat(a.x), s1 = fsplat(a.y);
#pragma unroll
            for (int p = 0; p < 6; p++) {
                acc[0][p] = ffma2(s0, bv[p], acc[0][p]);
                acc[1][p] = ffma2(s1, bv[p], acc[1][p]);
            }
        }
    }

#pragma unroll
    for (int m = 0; m < 2; m++) {
        int e1 = mg * 2 + m;
        float* dptr = g_D + ((size_t)((b * E_ + e1) * E_ + e2)) * CH + l0;
#pragma unroll
        for (int p = 0; p < 6; p++) *(ull*)(dptr + 2 * p) = acc[m][p];
    }
}

// ---------------------------------------------------------------- gather
__global__ void gather_kernel(const int* __restrict__ ht,
                              const float* __restrict__ bc,
                              float* __restrict__ out) {
    int idx = blockIdx.x * 256 + threadIdx.x;   // over 2048*96
    if (idx >= NROWS * CH) return;
    int n = idx / CH, l = idx - n * CH;
    int b  = n >> 7;
    int e1 = ht[2 * n];
    int e2 = ht[2 * n + 1];
    out[(size_t)n * L_ + l] =
        g_D[((size_t)((b * E_ + e1) * E_ + e2)) * CH + l] + bc[l];
}

// ---------------------------------------------------------------- launch
extern "C" void kernel_launch(void* const* d_in, const int* in_sizes, int n_in,
                              void* d_out, int out_size) {
    const float* feats = (const float*)d_in[0];
    const int*   pos   = (const int*)d_in[1];
    const int*   ht    = (const int*)d_in[2];
    const float* Wh    = (const float*)d_in[3];
    const float* bh    = (const float*)d_in[4];
    const float* Wt    = (const float*)d_in[5];
    const float* bt    = (const float*)d_in[6];
    const float* Wc    = (const float*)d_in[7];
    const float* bc    = (const float*)d_in[8];
    float*       out   = (float*)d_out;

    build_ent_kernel<<<NENT, 192>>>(feats, pos);

    dim3 g2(NENT / 64, H_ / 128, 2);
    gemm_tanh_kernel<<<g2, 256>>>(Wh, bh, Wt, bt);

    init_out_kernel<<<(NROWS * L_ + 255) / 256, 256>>>(bc, out);
    w96_extract_kernel<<<(KTOT + 255) / 256, 256>>>(Wc);

    dim3 g4(NROWS / 64, 12);
    l96_kernel<<<g4, 256>>>(ht, out);

    dim3 g5(12, 8, 32);
    stage1_kernel<<<g5, 256>>>(Wc);

    dim3 g6(B_, E_);
    stage2_kernel<<<g6, 128>>>();

    gather_kernel<<<(NROWS * CH + 255) / 256, 256>>>(ht, bc, out);
}

// round 9
// speedup vs baseline: 1.8973x; 1.0112x over previous
#include <cuda_runtime.h>
#include <cstdint>

// DocREDModel: entity-pool -> tanh-projection -> block-bilinear classifier
// B=16 S=2048 H=768 E=32 M=4 P=128 L=97 BLOCK=64
//
// Factorized pipeline:
//   C[e2, k1, l]    = sum_j zt[e2, cb*64+j] * Wc[(k1)*64+j, l]   k1=(cb,i)  (4.8 GF)
//   C96[e2, k1]     = sum_j zt[e2, cb*64+j] * Wc[(k1)*64+j, 96]             (50 MF)
//   D[b,e1,e2,l]    = sum_k1 zh[b*32+e1, k1] * C[b*32+e2, k1, l]            (2.4 GF)
//   D96[b,e1,e2]    = sum_k1 zh[b*32+e1, k1] * C96[b*32+e2, k1]             (25 MF)
//   out[n, l]       = (l<96 ? D[b,ht0,ht1,l] : D96[b,ht0,ht1]) + bc[l]

#define B_    16
#define S_    2048
#define H_    768
#define E_    32
#define L_    97
#define CH    96
#define NROWS 2048
#define NENT  512

typedef unsigned long long ull;

__device__ float g_ent[NENT * H_];
__device__ float g_zh[NENT * H_];
__device__ float g_zt[NENT * H_];
__device__ float g_C[(size_t)NENT * H_ * CH];      // 151 MB scratch
__device__ float g_C96[NENT * H_];                 // 1.5 MB
__device__ float g_D[B_ * E_ * E_ * CH];           // 6.3 MB
__device__ float g_D96[B_ * E_ * E_];

__device__ __forceinline__ ull ffma2(ull a, ull b, ull c) {
    ull d; asm("fma.rn.f32x2 %0, %1, %2, %3;" : "=l"(d) : "l"(a), "l"(b), "l"(c));
    return d;
}
__device__ __forceinline__ ull fsplat(float x) {
    ull d; asm("mov.b64 %0, {%1, %1};" : "=l"(d) : "f"(x));
    return d;
}
__device__ __forceinline__ float lo32(ull v) { return __uint_as_float((unsigned)(v & 0xffffffffull)); }
__device__ __forceinline__ float hi32(ull v) { return __uint_as_float((unsigned)(v >> 32)); }

// ---------------------------------------------------------------- kernel 1
__global__ void build_ent_kernel(const float* __restrict__ feats,
                                 const int* __restrict__ pos) {
    int be = blockIdx.x;
    int b  = be >> 5;
    const int* pp = pos + be * 4;
    int p0 = pp[0], p1 = pp[1], p2 = pp[2], p3 = pp[3];
    float w1 = (p1 != p0) ? 1.f : 0.f;
    float w2 = (p2 != p0 && p2 != p1) ? 1.f : 0.f;
    float w3 = (p3 != p0 && p3 != p1 && p3 != p2) ? 1.f : 0.f;
    const float* base = feats + (size_t)b * S_ * H_;
    const float4* r0 = (const float4*)(base + (size_t)p0 * H_);
    const float4* r1 = (const float4*)(base + (size_t)p1 * H_);
    const float4* r2 = (const float4*)(base + (size_t)p2 * H_);
    const float4* r3 = (const float4*)(base + (size_t)p3 * H_);
    int t = threadIdx.x;   // 192 threads * float4 = 768
    float4 v0 = r0[t], v1 = r1[t], v2 = r2[t], v3 = r3[t];
    float4 o;
    o.x = v0.x + w1 * v1.x + w2 * v2.x + w3 * v3.x;
    o.y = v0.y + w1 * v1.y + w2 * v2.y + w3 * v3.y;
    o.z = v0.z + w1 * v1.z + w2 * v2.z + w3 * v3.z;
    o.w = v0.w + w1 * v1.w + w2 * v2.w + w3 * v3.w;
    ((float4*)(g_ent + (size_t)be * H_))[t] = o;
}

// ---------------------------------------------------------------- kernel 2
__global__ void __launch_bounds__(256)
gemm_tanh_kernel(const float* __restrict__ Wh, const float* __restrict__ bh,
                 const float* __restrict__ Wt, const float* __restrict__ bt) {
    const float* W    = blockIdx.z ? Wt : Wh;
    const float* bias = blockIdx.z ? bt : bh;
    float*       Z    = blockIdx.z ? g_zt : g_zh;

    __shared__ float AsT[16 * 68];
    __shared__ float Bd[16 * 256];

    int tid = threadIdx.x;
    int mg  = tid & 15;
    int ng  = tid >> 4;
    int m0  = blockIdx.x * 64;
    int n0  = blockIdx.y * 128;

    ull acc[2][8];
#pragma unroll
    for (int p = 0; p < 2; p++)
#pragma unroll
        for (int c = 0; c < 8; c++) acc[p][c] = 0ull;

    for (int k0 = 0; k0 < H_; k0 += 16) {
        __syncthreads();
#pragma unroll
        for (int e = tid; e < 1024; e += 256) {
            int kk = e & 15, m = e >> 4;
            AsT[kk * 68 + m] = g_ent[(m0 + m) * H_ + k0 + kk];
        }
#pragma unroll
        for (int e = tid; e < 2048; e += 256) {
            int n = e & 127, kk = e >> 7;
            float w = W[(k0 + kk) * H_ + n0 + n];
            ((float2*)Bd)[kk * 128 + n] = make_float2(w, w);
        }
        __syncthreads();
#pragma unroll
        for (int kk = 0; kk < 16; kk++) {
            ulonglong2 av = *(const ulonglong2*)&AsT[kk * 68 + mg * 4];
            const ulonglong2* wp = (const ulonglong2*)&Bd[kk * 256 + ng * 16];
            ulonglong2 w01 = wp[0], w23 = wp[1], w45 = wp[2], w67 = wp[3];
            ull w[8] = {w01.x, w01.y, w23.x, w23.y, w45.x, w45.y, w67.x, w67.y};
#pragma unroll
            for (int c = 0; c < 8; c++) {
                acc[0][c] = ffma2(av.x, w[c], acc[0][c]);
                acc[1][c] = ffma2(av.y, w[c], acc[1][c]);
            }
        }
    }
#pragma unroll
    for (int p = 0; p < 2; p++) {
#pragma unroll
        for (int c = 0; c < 8; c++) {
            int n = n0 + ng * 8 + c;
            float bv = bias[n];
            int m = m0 + mg * 4 + 2 * p;
            Z[m * H_ + n]       = tanhf(lo32(acc[p][c]) + bv);
            Z[(m + 1) * H_ + n] = tanhf(hi32(acc[p][c]) + bv);
        }
    }
}

// ---------------------------------------------------------------- stage 1
// C[e2, cb*64+i, l] = sum_j zt[e2, cb*64+j] * Wc[((cb*64+i)*64+j)*97 + l]
// Grid (12 cb, 8 e2-tiles of 64, 32 il-tiles of 2i x 96l), 256 threads.
// NOTE: no min-CTA launch bound (avoid the 84-reg cap -> spills).
__global__ void __launch_bounds__(256)
stage1_kernel(const float* __restrict__ Wc) {
    __shared__ float As[64 * 68];      // [j][e2_loc], stride 68
    __shared__ float Bs[64 * 192];     // [j][i_loc*96 + l]

    int tid = threadIdx.x;
    int cb  = blockIdx.x;
    int e0  = blockIdx.y * 64;
    int i0  = blockIdx.z * 2;

    for (int e = tid; e < 4096; e += 256) {
        int j = e & 63, m = e >> 6;
        As[j * 68 + m] = g_zt[(e0 + m) * H_ + cb * 64 + j];
    }
    for (int e = tid; e < 12288; e += 256) {
        int row = e / 96, l = e - row * 96;     // row = i_loc*64 + j
        int il = row >> 6, j = row & 63;
        Bs[j * 192 + il * 96 + l] =
            Wc[(size_t)((cb * 64 + i0 + il) * 64 + j) * L_ + l];
    }
    __syncthreads();

    int mg = tid & 15;
    int ng = tid >> 4;
    int il = ng >> 3;
    int l0 = (ng & 7) * 12;
    const float* bptr = Bs + il * 96 + l0;
    const float* aptr = As + mg * 4;

    ull acc[4][6];
#pragma unroll
    for (int m = 0; m < 4; m++)
#pragma unroll
        for (int p = 0; p < 6; p++) acc[m][p] = 0ull;

#pragma unroll 4
    for (int k = 0; k < 64; k++) {
        float4 a = *(const float4*)(aptr + k * 68);
        ulonglong2 b01 = *(const ulonglong2*)(bptr + k * 192);
        ulonglong2 b23 = *(const ulonglong2*)(bptr + k * 192 + 4);
        ulonglong2 b45 = *(const ulonglong2*)(bptr + k * 192 + 8);
        ull bv[6] = {b01.x, b01.y, b23.x, b23.y, b45.x, b45.y};
        ull s0 = fsplat(a.x), s1 = fsplat(a.y), s2 = fsplat(a.z), s3 = fsplat(a.w);
#pragma unroll
        for (int p = 0; p < 6; p++) {
            acc[0][p] = ffma2(s0, bv[p], acc[0][p]);
            acc[1][p] = ffma2(s1, bv[p], acc[1][p]);
            acc[2][p] = ffma2(s2, bv[p], acc[2][p]);
            acc[3][p] = ffma2(s3, bv[p], acc[3][p]);
        }
    }

    int k1 = cb * 64 + i0 + il;
#pragma unroll
    for (int m = 0; m < 4; m++) {
        float* cptr = g_C + ((size_t)(e0 + mg * 4 + m) * H_ + k1) * CH + l0;
#pragma unroll
        for (int p = 0; p < 6; p++) *(ull*)(cptr + 2 * p) = acc[m][p];
    }
}

// ---------------------------------------------------------------- c96
// C96[e2, cb*64+i] = sum_j zt[e2, cb*64+j] * Wc[((cb*64+i)*64+j)*97 + 96]
// Grid (12 cb, 8 e2-tiles of 64), 256 threads: mg -> 4 e2 (2 pairs), ng -> 4 i.
__global__ void __launch_bounds__(256)
c96_kernel(const float* __restrict__ Wc) {
    __shared__ float zts[64 * 68];     // [j][e2]
    __shared__ float wts[64 * 64];     // [i][j]

    int tid = threadIdx.x;
    int cb  = blockIdx.x;
    int e0  = blockIdx.y * 64;

    for (int e = tid; e < 4096; e += 256) {
        int j = e & 63, m = e >> 6;
        zts[j * 68 + m] = g_zt[(e0 + m) * H_ + cb * 64 + j];
    }
    for (int e = tid; e < 4096; e += 256) {
        int i = e >> 6, j = e & 63;
        wts[i * 64 + j] = Wc[(size_t)((cb * 64 + i) * 64 + j) * L_ + 96];
    }
    __syncthreads();

    int mg = tid & 15;
    int i0 = (tid >> 4) * 4;

    ull acc[2][4];
#pragma unroll
    for (int p = 0; p < 2; p++)
#pragma unroll
        for (int i = 0; i < 4; i++) acc[p][i] = 0ull;

#pragma unroll 4
    for (int j = 0; j < 64; j++) {
        ulonglong2 a = *(const ulonglong2*)&zts[j * 68 + mg * 4];
#pragma unroll
        for (int i = 0; i < 4; i++) {
            ull w = fsplat(wts[(i0 + i) * 64 + j]);
            acc[0][i] = ffma2(a.x, w, acc[0][i]);
            acc[1][i] = ffma2(a.y, w, acc[1][i]);
        }
    }

#pragma unroll
    for (int p = 0; p < 2; p++) {
        int e2a = e0 + mg * 4 + 2 * p;
#pragma unroll
        for (int i = 0; i < 4; i++) {
            int k1 = cb * 64 + i0 + i;
            g_C96[e2a * H_ + k1]       = lo32(acc[p][i]);
            g_C96[(e2a + 1) * H_ + k1] = hi32(acc[p][i]);
        }
    }
}

// ---------------------------------------------------------------- stage 2
// D[b,e1,e2,l] = sum_k1 zh[b*32+e1,k1] * C[b*32+e2,k1,l]
// Grid (16 b, 32 e2, 2 l-halves), 128 threads, register-prefetch double buffer.
// mg=tid&15 -> 2 e1; ng=tid>>4 (8) -> 6 l (3 pairs).
__global__ void __launch_bounds__(128)
stage2_kernel() {
    __shared__ float As[64 * 36];      // [kk][e1]
    __shared__ float Bs[64 * 48];      // [kk][l-half]

    int tid = threadIdx.x;
    int b   = blockIdx.x;
    int e2  = blockIdx.y;
    int lh  = blockIdx.z;
    const float* crow = g_C + (size_t)(b * E_ + e2) * H_ * CH + lh * 48;
    const float* zrow = g_zh + (size_t)(b * E_) * H_;

    int mg = tid & 15;
    int ng = tid >> 4;
    int l0 = ng * 6;

    float  pa[16];
    float4 pb[6];
    // prefetch chunk 0
    {
#pragma unroll
        for (int s = 0; s < 16; s++) {
            int e = tid + s * 128, e1 = e >> 6, kk = e & 63;
            pa[s] = zrow[e1 * H_ + kk];
        }
#pragma unroll
        for (int s = 0; s < 6; s++) {
            int f = tid + s * 128, row = f / 12, col = f - row * 12;
            pb[s] = *(const float4*)(crow + (size_t)row * CH + col * 4);
        }
    }

    ull acc[2][3];
#pragma unroll
    for (int m = 0; m < 2; m++)
#pragma unroll
        for (int p = 0; p < 3; p++) acc[m][p] = 0ull;

    for (int kc = 0; kc < 12; kc++) {
        __syncthreads();               // prior compute done reading smem
#pragma unroll
        for (int s = 0; s < 16; s++) {
            int e = tid + s * 128, e1 = e >> 6, kk = e & 63;
            As[kk * 36 + e1] = pa[s];
        }
#pragma unroll
        for (int s = 0; s < 6; s++) {
            int f = tid + s * 128, row = f / 12, col = f - row * 12;
            *(float4*)&Bs[row * 48 + col * 4] = pb[s];
        }
        if (kc < 11) {                 // prefetch next chunk under compute
            const float* zc = zrow + (kc + 1) * 64;
            const float* cc = crow + (size_t)(kc + 1) * 64 * CH;
#pragma unroll
            for (int s = 0; s < 16; s++) {
                int e = tid + s * 128, e1 = e >> 6, kk = e & 63;
                pa[s] = zc[e1 * H_ + kk];
            }
#pragma unroll
            for (int s = 0; s < 6; s++) {
                int f = tid + s * 128, row = f / 12, col = f - row * 12;
                pb[s] = *(const float4*)(cc + (size_t)row * CH + col * 4);
            }
        }
        __syncthreads();               // smem ready

#pragma unroll 4
        for (int k = 0; k < 64; k++) {
            ull a = *(const ull*)&As[k * 36 + mg * 2];
            ull s0 = fsplat(lo32(a));
            ull s1 = fsplat(hi32(a));
            ull b0 = *(const ull*)&Bs[k * 48 + l0];
            ull b1 = *(const ull*)&Bs[k * 48 + l0 + 2];
            ull b2 = *(const ull*)&Bs[k * 48 + l0 + 4];
            acc[0][0] = ffma2(s0, b0, acc[0][0]);
            acc[1][0] = ffma2(s1, b0, acc[1][0]);
            acc[0][1] = ffma2(s0, b1, acc[0][1]);
            acc[1][1] = ffma2(s1, b1, acc[1][1]);
            acc[0][2] = ffma2(s0, b2, acc[0][2]);
            acc[1][2] = ffma2(s1, b2, acc[1][2]);
        }
    }

#pragma unroll
    for (int m = 0; m < 2; m++) {
        int e1 = mg * 2 + m;
        float* dptr = g_D + (size_t)((b * E_ + e1) * E_ + e2) * CH + lh * 48 + l0;
#pragma unroll
        for (int p = 0; p < 3; p++) *(ull*)(dptr + 2 * p) = acc[m][p];
    }
}

// ---------------------------------------------------------------- d96
// D96[b,e1,e2] = sum_k zh[b*32+e1,k] * C96[b*32+e2,k].  Grid (16,32), 128 thr.
__global__ void __launch_bounds__(128)
d96_kernel() {
    __shared__ float c96s[H_];
    int b  = blockIdx.x;
    int e2 = blockIdx.y;
    int tid = threadIdx.x;
    const float* crow = g_C96 + (size_t)(b * E_ + e2) * H_;
    for (int s = tid; s < H_ / 4; s += 128)
        ((float4*)c96s)[s] = ((const float4*)crow)[s];
    __syncthreads();

    int e1 = tid >> 2, q = tid & 3;
    const float* zr = g_zh + (size_t)(b * E_ + e1) * H_;
    float acc = 0.f;
#pragma unroll 8
    for (int k = q; k < H_; k += 4) acc += zr[k] * c96s[k];
    acc += __shfl_down_sync(0xffffffffu, acc, 2, 4);
    acc += __shfl_down_sync(0xffffffffu, acc, 1, 4);
    if (q == 0) g_D96[(b * E_ + e1) * E_ + e2] = acc;
}

// ---------------------------------------------------------------- gather
__global__ void gather_kernel(const int* __restrict__ ht,
                              const float* __restrict__ bc,
                              float* __restrict__ out) {
    int idx = blockIdx.x * 256 + threadIdx.x;
    if (idx >= NROWS * L_) return;
    int n = idx / L_, l = idx - n * L_;
    int b  = n >> 7;
    int e1 = ht[2 * n];
    int e2 = ht[2 * n + 1];
    int pe = (b * E_ + e1) * E_ + e2;
    float v = (l < CH) ? g_D[(size_t)pe * CH + l] : g_D96[pe];
    out[idx] = v + bc[l];
}

// ---------------------------------------------------------------- launch
extern "C" void kernel_launch(void* const* d_in, const int* in_sizes, int n_in,
                              void* d_out, int out_size) {
    const float* feats = (const float*)d_in[0];
    const int*   pos   = (const int*)d_in[1];
    const int*   ht    = (const int*)d_in[2];
    const float* Wh    = (const float*)d_in[3];
    const float* bh    = (const float*)d_in[4];
    const float* Wt    = (const float*)d_in[5];
    const float* bt    = (const float*)d_in[6];
    const float* Wc    = (const float*)d_in[7];
    const float* bc    = (const float*)d_in[8];
    float*       out   = (float*)d_out;

    build_ent_kernel<<<NENT, 192>>>(feats, pos);

    dim3 g2(NENT / 64, H_ / 128, 2);
    gemm_tanh_kernel<<<g2, 256>>>(Wh, bh, Wt, bt);

    dim3 g5(12, 8, 32);
    stage1_kernel<<<g5, 256>>>(Wc);

    dim3 gc(12, 8);
    c96_kernel<<<gc, 256>>>(Wc);

    dim3 g6(B_, E_, 2);
    stage2_kernel<<<g6, 128>>>();

    dim3 gd(B_, E_);
    d96_kernel<<<gd, 128>>>();

    gather_kernel<<<(NROWS * L_ + 255) / 256, 256>>>(ht, bc, out);
}